// round 12
// baseline (speedup 1.0000x reference)
#include <cuda_runtime.h>

#define NBIN 256
#define EPSF 1e-10f
#define CHUNK_LG 12
#define CHUNK (1 << CHUNK_LG)          // 4096 elements per chunk
#define MAXN 67108864                  // 4*256^3
#define MAXCHUNK (MAXN / CHUNK)        // 16384
#define FT 4096                        // fold tile (floats)

// ---------------- device scratch (static; no runtime allocation) ----------------
__device__ unsigned int g_min_ord;
__device__ unsigned int g_cnt0[256 * MAXCHUNK];   // [bin*nchunk + chunk]
__device__ unsigned int g_cnt1[256 * MAXCHUNK];
__device__ unsigned int g_bs0[NBIN + 1];          // global group starts
__device__ unsigned int g_bs1[NBIN + 1];
__device__ unsigned char g_sidx0[MAXN];           // staged bin index
__device__ unsigned char g_sidx1[MAXN];
__device__ float g_sd0[MAXN];                     // staged d (-1 = not kept)
__device__ float g_sd1[MAXN];
__device__ float g_sorted0[MAXN];                 // d values, stably sorted by bin
__device__ float g_sorted1[MAXN];
__device__ float g_h0[NBIN];
__device__ float g_h1[NBIN];

// Order-preserving float<->uint so unsigned atomicMin == float min.
__device__ __forceinline__ unsigned int f2ord(float f) {
    unsigned int u = __float_as_uint(f);
    return (u & 0x80000000u) ? ~u : (u | 0x80000000u);
}
__device__ __forceinline__ float ord2f(unsigned int o) {
    return __uint_as_float((o & 0x80000000u) ? (o & 0x7FFFFFFFu) : ~o);
}

// ---------------- Cephes-style f32 log/exp (XLA:CPU lineage, FMA form) ----------
__device__ __forceinline__ float xla_logf(float x) {
    unsigned int ix = __float_as_uint(x);
    int e = (int)(ix >> 23) - 126;
    float m = __uint_as_float((ix & 0x007FFFFFu) | 0x3F000000u);   // [0.5, 1)
    float ef = (float)e;
    if (m < 0.707106781186547524f) { ef -= 1.0f; m = m + m; }      // exact
    float xm = m - 1.0f;                                           // exact
    float z = __fmul_rn(xm, xm);
    float y = 7.0376836292E-2f;
    y = __fmaf_rn(y, xm, -1.1514610310E-1f);
    y = __fmaf_rn(y, xm,  1.1676998740E-1f);
    y = __fmaf_rn(y, xm, -1.2420140846E-1f);
    y = __fmaf_rn(y, xm,  1.4249322787E-1f);
    y = __fmaf_rn(y, xm, -1.6668057665E-1f);
    y = __fmaf_rn(y, xm,  2.0000714765E-1f);
    y = __fmaf_rn(y, xm, -2.4999993993E-1f);
    y = __fmaf_rn(y, xm,  3.3333331174E-1f);
    y = __fmul_rn(y, xm);
    y = __fmul_rn(y, z);
    y = __fmaf_rn(ef, -2.12194440e-4f, y);
    y = __fmaf_rn(z, -0.5f, y);
    float r = __fadd_rn(xm, y);
    r = __fmaf_rn(ef, 0.693359375f, r);
    return r;
}
__device__ __forceinline__ float xla_expf(float x) {
    x = fminf(x, 88.723164f);
    x = fmaxf(x, -88.723164f);
    float m = floorf(__fmaf_rn(x, 1.44269504088896341f, 0.5f));
    float r = __fmaf_rn(m, -0.693359375f, x);
    r = __fmaf_rn(m, 2.12194440e-4f, r);
    float r2 = __fmul_rn(r, r);
    float p = 1.9875691500E-4f;
    p = __fmaf_rn(p, r, 1.3981999507E-3f);
    p = __fmaf_rn(p, r, 8.3334519073E-3f);
    p = __fmaf_rn(p, r, 4.1665795894E-2f);
    p = __fmaf_rn(p, r, 1.6666665459E-1f);
    p = __fmaf_rn(p, r, 5.0000001201E-1f);
    float y = __fmaf_rn(p, r2, r);
    y = __fadd_rn(y, 1.0f);
    int mi = (int)m;
    return __fmul_rn(y, __uint_as_float((unsigned int)(mi + 127) << 23));
}

// ---------------- kernel 0: reset min ----------------
__global__ void k_init() { g_min_ord = 0xFFFFFFFFu; }

// ---------------- kernel 1: global min of img0 (float4) ----------------
__global__ void k_min(const float4* __restrict__ img, int n4) {
    float m = 3.402823466e38f;
    int stride = gridDim.x * blockDim.x;
    for (int i = blockIdx.x * blockDim.x + threadIdx.x; i < n4; i += stride) {
        float4 v = img[i];
        m = fminf(m, fminf(fminf(v.x, v.y), fminf(v.z, v.w)));
    }
    #pragma unroll
    for (int o = 16; o; o >>= 1) m = fminf(m, __shfl_xor_sync(0xFFFFFFFFu, m, o));
    __shared__ float sm[32];
    int lane = threadIdx.x & 31, w = threadIdx.x >> 5;
    if (lane == 0) sm[w] = m;
    __syncthreads();
    if (w == 0) {
        int nw = (blockDim.x + 31) >> 5;
        m = (lane < nw) ? sm[lane] : 3.402823466e38f;
        #pragma unroll
        for (int o = 16; o; o >>= 1) m = fminf(m, __shfl_xor_sync(0xFFFFFFFFu, m, o));
        if (lane == 0) atomicMin(&g_min_ord, f2ord(m));
    }
}

// ---------------- binning math (bit-exact vs reference; div only when kept) ----
__device__ __forceinline__ void stage_one(float v, float hmin, float dh,
                                          unsigned char& idx8, float& dout) {
    if (v >= hmin && v <= 0.0f) {
        float x  = __fdiv_rn(v - hmin, dh);
        float fi = floorf(x);
        idx8 = (unsigned char)(int)fi;
        dout = x - fi;                 // exact; in [0,1)
    } else {
        idx8 = 0;
        dout = -1.0f;                  // sentinel: not kept
    }
}

// ---------------- kernel 2: stage (bin once) + per-(bin,chunk) counts ----------
// block per chunk; float4 loads; writes staged (idx,d) coalesced.
__global__ void k_stage(const float4* __restrict__ i0, const float4* __restrict__ i1,
                        int n, int nchunk) {
    __shared__ unsigned int sc0[256], sc1[256];
    int t = threadIdx.x;
    sc0[t] = 0u; sc1[t] = 0u;
    __syncthreads();

    float hmin = ord2f(g_min_ord);
    float dh   = __fdiv_rn(0.0f - hmin, 255.0f);
    int chunk = blockIdx.x;
    int base4 = (chunk << CHUNK_LG) >> 2;          // float4 index base

    #pragma unroll
    for (int wv = 0; wv < (CHUNK / 1024); wv++) {  // 4 waves of 256 float4s
        int i4 = base4 + (wv << 8) + t;
        if (i4 * 4 < n) {
            float4 a = i0[i4];
            float4 b = i1[i4];
            unsigned char ia0, ia1, ia2, ia3, ib0, ib1, ib2, ib3;
            float da0, da1, da2, da3, db0, db1, db2, db3;
            stage_one(a.x, hmin, dh, ia0, da0);
            stage_one(a.y, hmin, dh, ia1, da1);
            stage_one(a.z, hmin, dh, ia2, da2);
            stage_one(a.w, hmin, dh, ia3, da3);
            stage_one(b.x, hmin, dh, ib0, db0);
            stage_one(b.y, hmin, dh, ib1, db1);
            stage_one(b.z, hmin, dh, ib2, db2);
            stage_one(b.w, hmin, dh, ib3, db3);
            if (da0 >= 0.0f) atomicAdd(&sc0[ia0], 1u);
            if (da1 >= 0.0f) atomicAdd(&sc0[ia1], 1u);
            if (da2 >= 0.0f) atomicAdd(&sc0[ia2], 1u);
            if (da3 >= 0.0f) atomicAdd(&sc0[ia3], 1u);
            if (db0 >= 0.0f) atomicAdd(&sc1[ib0], 1u);
            if (db1 >= 0.0f) atomicAdd(&sc1[ib1], 1u);
            if (db2 >= 0.0f) atomicAdd(&sc1[ib2], 1u);
            if (db3 >= 0.0f) atomicAdd(&sc1[ib3], 1u);
            ((uchar4*)g_sidx0)[i4] = make_uchar4(ia0, ia1, ia2, ia3);
            ((uchar4*)g_sidx1)[i4] = make_uchar4(ib0, ib1, ib2, ib3);
            ((float4*)g_sd0)[i4] = make_float4(da0, da1, da2, da3);
            ((float4*)g_sd1)[i4] = make_float4(db0, db1, db2, db3);
        }
    }
    __syncthreads();
    g_cnt0[t * nchunk + chunk] = sc0[t];
    g_cnt1[t * nchunk + chunk] = sc1[t];
}

// ---------------- kernel 3: scan counts -> global start offsets ----------------
__global__ void k_scan(int nchunk) {
    int img = threadIdx.x >> 8;
    int b   = threadIdx.x & 255;
    unsigned int* cnt = img ? g_cnt1 : g_cnt0;
    unsigned int* bs  = img ? g_bs1  : g_bs0;

    unsigned int tot = 0;
    for (int c = 0; c < nchunk; c++) tot += cnt[b * nchunk + c];

    __shared__ unsigned int s_tot[512];
    s_tot[threadIdx.x] = tot;
    __syncthreads();
    if (b == 0) {
        unsigned int run = 0;
        for (int j = 0; j < 256; j++) {
            unsigned int v = s_tot[(img << 8) + j];
            s_tot[(img << 8) + j] = run;
            run += v;
        }
        bs[256] = run;
    }
    __syncthreads();
    unsigned int run = s_tot[threadIdx.x];
    bs[b] = run;
    for (int c = 0; c < nchunk; c++) {
        unsigned int v = cnt[b * nchunk + c];
        cnt[b * nchunk + c] = run;
        run += v;
    }
}

// ---------------- kernel 4: stable placement from staged data ----------------
// grid (nchunk, 2), 256 threads. Ordering tid-based => deterministic/stable.
__global__ void k_place(int n, int nchunk) {
    __shared__ unsigned int s_start[256];
    __shared__ __align__(16) unsigned short s_wc[256][8];   // per (bin, warp) counts

    int img = blockIdx.y;
    const unsigned char* __restrict__ sidx = img ? g_sidx1 : g_sidx0;
    const float* __restrict__ sdv = img ? g_sd1 : g_sd0;
    const unsigned int* cnt = img ? g_cnt1 : g_cnt0;
    float* outp = img ? g_sorted1 : g_sorted0;

    int chunk = blockIdx.x;
    int base  = chunk << CHUNK_LG;
    int t     = threadIdx.x;
    int lane  = t & 31, w = t >> 5;

    s_start[t] = cnt[t * nchunk + chunk];
    *(uint4*)&s_wc[t][0] = make_uint4(0u, 0u, 0u, 0u);
    __syncthreads();

    #pragma unroll 1
    for (int wv = 0; wv < (CHUNK / 256); wv++) {
        int i = base + (wv << 8) + t;
        float d = (i < n) ? sdv[i] : -1.0f;
        int idx = (i < n) ? (int)sidx[i] : 0;
        bool keep = (d >= 0.0f);

        unsigned int key = keep ? (unsigned int)idx : (0x1000u + (unsigned int)t);
        unsigned int mask = __match_any_sync(0xFFFFFFFFu, key);
        int rank = __popc(mask & ((1u << lane) - 1u));
        if (keep && rank == 0) s_wc[idx][w] = (unsigned short)__popc(mask);
        __syncthreads();

        if (keep) {
            unsigned int off = s_start[idx] + (unsigned int)rank;
            for (int w2 = 0; w2 < w; w2++) off += (unsigned int)s_wc[idx][w2];
            outp[off] = d;
        }
        __syncthreads();

        // thread t owns bin t: advance start, clear counts
        uint4 packed = *(uint4*)&s_wc[t][0];
        const unsigned short* wc = (const unsigned short*)&packed;
        unsigned int tot = 0;
        #pragma unroll
        for (int k = 0; k < 8; k++) tot += wc[k];
        if (tot) {
            s_start[t] += tot;
            *(uint4*)&s_wc[t][0] = make_uint4(0u, 0u, 0u, 0u);
        }
        __syncthreads();
    }
}

// ---------------- kernel 5: exact sequential f32 fold, staged through smem -----
// grid (256, 2), 160 threads. Loaders (t>=32) stage double-buffered tiles with
// the weight transform applied (same __fsub_rn bits). Folder = warp0 lane0,
// compile-time float4 loop: 4 cyc/elem dependency chain, bit-identical order.
__global__ void k_fold() {
    __shared__ __align__(16) float buf[2][FT];
    int img = blockIdx.y;
    const float* __restrict__ sd = img ? g_sorted1 : g_sorted0;
    const unsigned int* bs = img ? g_bs1 : g_bs0;
    float* h = img ? g_h1 : g_h0;
    int b = blockIdx.x;
    int t = threadIdx.x;

    unsigned int sA = bs[b], eA = bs[b + 1];
    unsigned int nA = eA - sA;                       // group b   -> weight (1-d)
    unsigned int sB = (b > 0) ? bs[b - 1] : 0u;
    unsigned int nB = (b > 0) ? (bs[b] - sB) : 0u;   // group b-1 -> weight d
    unsigned int total = nA + nB;
    int ntile = (int)((total + FT - 1) / FT);

    // stage tile 0
    if (t >= 32 && ntile > 0) {
        unsigned int lim = (total < (unsigned int)FT) ? total : (unsigned int)FT;
        #pragma unroll 4
        for (unsigned int j = (unsigned int)(t - 32); j < lim; j += 128u)
            buf[0][j] = (j < nA) ? __fsub_rn(1.0f, sd[sA + j])
                                 : sd[sB + (j - nA)];
    }
    __syncthreads();

    float acc = 0.0f;
    for (int k = 0; k < ntile; k++) {
        int cur = k & 1;
        if (t >= 32) {
            if (k + 1 < ntile) {                     // prefetch next tile
                unsigned int nb = (unsigned int)(k + 1) * FT;
                unsigned int rem = total - nb;
                unsigned int lim = (rem < (unsigned int)FT) ? rem : (unsigned int)FT;
                #pragma unroll 4
                for (unsigned int j = (unsigned int)(t - 32); j < lim; j += 128u) {
                    unsigned int jj = nb + j;
                    buf[cur ^ 1][j] = (jj < nA) ? __fsub_rn(1.0f, sd[sA + jj])
                                                : sd[sB + (jj - nA)];
                }
            }
        } else if (t == 0) {
            unsigned int rem = total - (unsigned int)k * FT;
            if (rem >= (unsigned int)FT) {
                const float4* __restrict__ B4 = (const float4*)buf[cur];
                #pragma unroll 4
                for (int i = 0; i < FT / 4; i++) {
                    float4 v = B4[i];
                    acc = __fadd_rn(acc, v.x);
                    acc = __fadd_rn(acc, v.y);
                    acc = __fadd_rn(acc, v.z);
                    acc = __fadd_rn(acc, v.w);
                }
            } else {
                const float* __restrict__ B = buf[cur];
                for (unsigned int i = 0; i < rem; i++)
                    acc = __fadd_rn(acc, B[i]);
            }
        }
        __syncthreads();
    }
    if (t == 0) h[b] = acc;
}

// ---------------- kernel 6: finalize (single thread, reference op-order) -------
__global__ void k_final(float* __restrict__ out) {
    if (threadIdx.x != 0 || blockIdx.x != 0) return;

    float S0 = 0.0f, S1 = 0.0f;
    for (int t = 0; t < NBIN; t++) S0 = __fadd_rn(S0, g_h0[t]);
    for (int t = 0; t < NBIN; t++) S1 = __fadd_rn(S1, g_h1[t]);

    float d0 = __fadd_rn(S0, EPSF);
    float d1 = __fadd_rn(S1, EPSF);

    float acc = 0.0f;
    for (int t = 0; t < NBIN; t++) {
        float h0n = __fdiv_rn(__fadd_rn(g_h0[t], EPSF), d0);
        float h1n = __fdiv_rn(__fadd_rn(g_h1[t], EPSF), d1);
        float num = __fadd_rn(h1n, EPSF);
        float qi  = __fdiv_rn(num, h1n);
        float qt  = __fdiv_rn(num, h0n);
        float inp = xla_logf(qi);
        float tgt = xla_logf(qt);
        float et  = xla_expf(tgt);
        float term = __fmul_rn(et, __fsub_rn(tgt, inp));
        acc = __fadd_rn(acc, term);
    }
    out[0] = __fdiv_rn(acc, 256.0f);
}

// ---------------- launch ----------------
extern "C" void kernel_launch(void* const* d_in, const int* in_sizes, int n_in,
                              void* d_out, int out_size) {
    const float* img0 = (const float*)d_in[0];
    const float* img1 = (const float*)d_in[1];
    float* out = (float*)d_out;
    int n = in_sizes[0];
    if (n > MAXN) n = MAXN;
    int nchunk = (n + CHUNK - 1) / CHUNK;

    k_init <<<1, 1>>>();
    k_min  <<<1184, 256>>>((const float4*)img0, n >> 2);
    k_stage<<<nchunk, 256>>>((const float4*)img0, (const float4*)img1, n, nchunk);
    k_scan <<<1, 512>>>(nchunk);
    k_place<<<dim3(nchunk, 2), 256>>>(n, nchunk);
    k_fold <<<dim3(256, 2), 160>>>();
    k_final<<<1, 32>>>(out);
}

// round 13
// speedup vs baseline: 1.5943x; 1.5943x over previous
#include <cuda_runtime.h>

#define NBIN 256
#define EPSF 1e-10f
#define CH_LG 10
#define CH (1 << CH_LG)                // 1024 elements per chunk
#define MAXN 67108864                  // 4*256^3
#define MAXCHUNK (MAXN / CH)           // 65536
#define FT 4096                        // fold tile (floats)

// ---------------- device scratch (static; no runtime allocation) ----------------
__device__ unsigned int g_min_ord;
__device__ unsigned int g_cnt0[MAXCHUNK * 256];   // [chunk][bin]  (transposed!)
__device__ unsigned int g_cnt1[MAXCHUNK * 256];
__device__ unsigned int g_bs0[NBIN + 1];          // global group starts
__device__ unsigned int g_bs1[NBIN + 1];
__device__ unsigned char g_sidx0[MAXN];           // staged bin index
__device__ unsigned char g_sidx1[MAXN];
__device__ float g_sd0[MAXN];                     // staged d (-1 = not kept)
__device__ float g_sd1[MAXN];
__device__ float g_sorted0[MAXN];                 // d values, stably sorted by bin
__device__ float g_sorted1[MAXN];
__device__ float g_h0[NBIN];
__device__ float g_h1[NBIN];

// Order-preserving float<->uint so unsigned atomicMin == float min.
__device__ __forceinline__ unsigned int f2ord(float f) {
    unsigned int u = __float_as_uint(f);
    return (u & 0x80000000u) ? ~u : (u | 0x80000000u);
}
__device__ __forceinline__ float ord2f(unsigned int o) {
    return __uint_as_float((o & 0x80000000u) ? (o & 0x7FFFFFFFu) : ~o);
}

// ---------------- Cephes-style f32 log/exp (XLA:CPU lineage, FMA form) ----------
__device__ __forceinline__ float xla_logf(float x) {
    unsigned int ix = __float_as_uint(x);
    int e = (int)(ix >> 23) - 126;
    float m = __uint_as_float((ix & 0x007FFFFFu) | 0x3F000000u);   // [0.5, 1)
    float ef = (float)e;
    if (m < 0.707106781186547524f) { ef -= 1.0f; m = m + m; }      // exact
    float xm = m - 1.0f;                                           // exact
    float z = __fmul_rn(xm, xm);
    float y = 7.0376836292E-2f;
    y = __fmaf_rn(y, xm, -1.1514610310E-1f);
    y = __fmaf_rn(y, xm,  1.1676998740E-1f);
    y = __fmaf_rn(y, xm, -1.2420140846E-1f);
    y = __fmaf_rn(y, xm,  1.4249322787E-1f);
    y = __fmaf_rn(y, xm, -1.6668057665E-1f);
    y = __fmaf_rn(y, xm,  2.0000714765E-1f);
    y = __fmaf_rn(y, xm, -2.4999993993E-1f);
    y = __fmaf_rn(y, xm,  3.3333331174E-1f);
    y = __fmul_rn(y, xm);
    y = __fmul_rn(y, z);
    y = __fmaf_rn(ef, -2.12194440e-4f, y);
    y = __fmaf_rn(z, -0.5f, y);
    float r = __fadd_rn(xm, y);
    r = __fmaf_rn(ef, 0.693359375f, r);
    return r;
}
__device__ __forceinline__ float xla_expf(float x) {
    x = fminf(x, 88.723164f);
    x = fmaxf(x, -88.723164f);
    float m = floorf(__fmaf_rn(x, 1.44269504088896341f, 0.5f));
    float r = __fmaf_rn(m, -0.693359375f, x);
    r = __fmaf_rn(m, 2.12194440e-4f, r);
    float r2 = __fmul_rn(r, r);
    float p = 1.9875691500E-4f;
    p = __fmaf_rn(p, r, 1.3981999507E-3f);
    p = __fmaf_rn(p, r, 8.3334519073E-3f);
    p = __fmaf_rn(p, r, 4.1665795894E-2f);
    p = __fmaf_rn(p, r, 1.6666665459E-1f);
    p = __fmaf_rn(p, r, 5.0000001201E-1f);
    float y = __fmaf_rn(p, r2, r);
    y = __fadd_rn(y, 1.0f);
    int mi = (int)m;
    return __fmul_rn(y, __uint_as_float((unsigned int)(mi + 127) << 23));
}

// ---------------- kernel 0: reset min ----------------
__global__ void k_init() { g_min_ord = 0xFFFFFFFFu; }

// ---------------- kernel 1: global min of img0 (float4) ----------------
__global__ void k_min(const float4* __restrict__ img, int n4) {
    float m = 3.402823466e38f;
    int stride = gridDim.x * blockDim.x;
    for (int i = blockIdx.x * blockDim.x + threadIdx.x; i < n4; i += stride) {
        float4 v = img[i];
        m = fminf(m, fminf(fminf(v.x, v.y), fminf(v.z, v.w)));
    }
    #pragma unroll
    for (int o = 16; o; o >>= 1) m = fminf(m, __shfl_xor_sync(0xFFFFFFFFu, m, o));
    __shared__ float sm[32];
    int lane = threadIdx.x & 31, w = threadIdx.x >> 5;
    if (lane == 0) sm[w] = m;
    __syncthreads();
    if (w == 0) {
        int nw = (blockDim.x + 31) >> 5;
        m = (lane < nw) ? sm[lane] : 3.402823466e38f;
        #pragma unroll
        for (int o = 16; o; o >>= 1) m = fminf(m, __shfl_xor_sync(0xFFFFFFFFu, m, o));
        if (lane == 0) atomicMin(&g_min_ord, f2ord(m));
    }
}

// ---------------- binning math (bit-exact vs reference; div only when kept) ----
__device__ __forceinline__ void stage_one(float v, float hmin, float dh,
                                          unsigned char& idx8, float& dout) {
    if (v >= hmin && v <= 0.0f) {
        float x  = __fdiv_rn(v - hmin, dh);
        float fi = floorf(x);
        idx8 = (unsigned char)(int)fi;
        dout = x - fi;                 // exact; in [0,1)
    } else {
        idx8 = 0;
        dout = -1.0f;                  // sentinel: not kept
    }
}

// ---------------- kernel 2: stage (bin once) + per-(chunk,bin) counts ----------
// block per 1024-elem chunk; one float4 per image per thread.
__global__ void k_stage(const float4* __restrict__ i0, const float4* __restrict__ i1,
                        int n) {
    __shared__ unsigned int sc0[256], sc1[256];
    int t = threadIdx.x;
    sc0[t] = 0u; sc1[t] = 0u;
    __syncthreads();

    float hmin = ord2f(g_min_ord);
    float dh   = __fdiv_rn(0.0f - hmin, 255.0f);
    int chunk = blockIdx.x;
    int i4 = (chunk << (CH_LG - 2)) + t;           // float4 index

    if (i4 * 4 < n) {
        float4 a = i0[i4];
        float4 b = i1[i4];
        unsigned char ia0, ia1, ia2, ia3, ib0, ib1, ib2, ib3;
        float da0, da1, da2, da3, db0, db1, db2, db3;
        stage_one(a.x, hmin, dh, ia0, da0);
        stage_one(a.y, hmin, dh, ia1, da1);
        stage_one(a.z, hmin, dh, ia2, da2);
        stage_one(a.w, hmin, dh, ia3, da3);
        stage_one(b.x, hmin, dh, ib0, db0);
        stage_one(b.y, hmin, dh, ib1, db1);
        stage_one(b.z, hmin, dh, ib2, db2);
        stage_one(b.w, hmin, dh, ib3, db3);
        if (da0 >= 0.0f) atomicAdd(&sc0[ia0], 1u);
        if (da1 >= 0.0f) atomicAdd(&sc0[ia1], 1u);
        if (da2 >= 0.0f) atomicAdd(&sc0[ia2], 1u);
        if (da3 >= 0.0f) atomicAdd(&sc0[ia3], 1u);
        if (db0 >= 0.0f) atomicAdd(&sc1[ib0], 1u);
        if (db1 >= 0.0f) atomicAdd(&sc1[ib1], 1u);
        if (db2 >= 0.0f) atomicAdd(&sc1[ib2], 1u);
        if (db3 >= 0.0f) atomicAdd(&sc1[ib3], 1u);
        ((uchar4*)g_sidx0)[i4] = make_uchar4(ia0, ia1, ia2, ia3);
        ((uchar4*)g_sidx1)[i4] = make_uchar4(ib0, ib1, ib2, ib3);
        ((float4*)g_sd0)[i4] = make_float4(da0, da1, da2, da3);
        ((float4*)g_sd1)[i4] = make_float4(db0, db1, db2, db3);
    }
    __syncthreads();
    g_cnt0[chunk * 256 + t] = sc0[t];              // coalesced [chunk][bin]
    g_cnt1[chunk * 256 + t] = sc1[t];
}

// ---------------- kernel 3: scan counts -> global start offsets ----------------
// [chunk][bin] layout: both passes fully coalesced (warp = 32 consecutive bins).
__global__ void k_scan(int nchunk) {
    int img = threadIdx.x >> 8;
    int b   = threadIdx.x & 255;
    unsigned int* cnt = img ? g_cnt1 : g_cnt0;
    unsigned int* bs  = img ? g_bs1  : g_bs0;

    unsigned int tot = 0;
    for (int c = 0; c < nchunk; c++) tot += cnt[c * 256 + b];

    __shared__ unsigned int s_tot[512];
    s_tot[threadIdx.x] = tot;
    __syncthreads();
    if (b == 0) {
        unsigned int run = 0;
        for (int j = 0; j < 256; j++) {
            unsigned int v = s_tot[(img << 8) + j];
            s_tot[(img << 8) + j] = run;
            run += v;
        }
        bs[256] = run;
    }
    __syncthreads();
    unsigned int run = s_tot[threadIdx.x];
    bs[b] = run;
    for (int c = 0; c < nchunk; c++) {
        unsigned int v = cnt[c * 256 + b];
        cnt[c * 256 + b] = run;                    // rewrite to global start
        run += v;
    }
}

// ---------------- kernel 4: stable placement, 3 barriers per 1024 elems --------
// grid (nchunk, 2), 256 threads, 4 elems/thread. Segment = (wave, warp):
// element order = (wave, warp, lane) lexicographic => stability preserved.
__global__ void k_place(int n) {
    __shared__ unsigned short s_cnt[32][256];      // [segment][bin] counts->starts
    __shared__ unsigned int s_gs[256];             // global starts for this chunk

    int img = blockIdx.y;
    const unsigned char* __restrict__ sidx = img ? g_sidx1 : g_sidx0;
    const float* __restrict__ sdv = img ? g_sd1 : g_sd0;
    const unsigned int* __restrict__ cnt = img ? g_cnt1 : g_cnt0;
    float* __restrict__ outp = img ? g_sorted1 : g_sorted0;

    int chunk = blockIdx.x;
    int base  = chunk << CH_LG;
    int t     = threadIdx.x;
    int lane  = t & 31, w = t >> 5;

    // zero count table (16KB = 4096 u32)
    #pragma unroll
    for (int k = 0; k < 16; k++)
        ((unsigned int*)s_cnt)[t + (k << 8)] = 0u;
    s_gs[t] = cnt[chunk * 256 + t];                // coalesced
    __syncthreads();

    // phase 1: match-based per-(segment,bin) counts; ranks/d kept in registers
    int   idxs[4];
    int   ranks[4];
    float ds[4];
    #pragma unroll
    for (int wv = 0; wv < 4; wv++) {
        int i = base + (wv << 8) + t;
        float d = (i < n) ? sdv[i] : -1.0f;
        int idx = (i < n) ? (int)sidx[i] : 0;
        bool keep = (d >= 0.0f);
        unsigned int key = keep ? (unsigned int)idx : (0x1000u + (unsigned int)lane);
        unsigned int mask = __match_any_sync(0xFFFFFFFFu, key);
        int rank = __popc(mask & ((1u << lane) - 1u));
        int seg = (wv << 3) + w;
        if (keep && rank == 0)
            s_cnt[seg][idx] = (unsigned short)__popc(mask);
        idxs[wv] = idx; ranks[wv] = rank; ds[wv] = d;
    }
    __syncthreads();

    // phase 2: thread t owns bin t; exclusive prefix over 32 segments in regs
    {
        unsigned int c[32];
        #pragma unroll
        for (int s = 0; s < 32; s++) c[s] = s_cnt[s][t];
        unsigned int run = 0;
        #pragma unroll
        for (int s = 0; s < 32; s++) { unsigned int v = c[s]; c[s] = run; run += v; }
        #pragma unroll
        for (int s = 0; s < 32; s++) s_cnt[s][t] = (unsigned short)c[s];
    }
    __syncthreads();

    // phase 3: write out
    #pragma unroll
    for (int wv = 0; wv < 4; wv++) {
        if (ds[wv] >= 0.0f) {
            int seg = (wv << 3) + w;
            int idx = idxs[wv];
            unsigned int off = s_gs[idx] + (unsigned int)s_cnt[seg][idx]
                             + (unsigned int)ranks[wv];
            outp[off] = ds[wv];
        }
    }
}

// ---------------- kernel 5: exact sequential f32 fold, staged through smem -----
// grid (256, 2), 160 threads. Loaders (t>=32) stage double-buffered tiles with
// the weight transform applied (same __fsub_rn bits). Folder = warp0 lane0,
// compile-time float4 loop: 4 cyc/elem dependency chain, bit-identical order.
__global__ void k_fold() {
    __shared__ __align__(16) float buf[2][FT];
    int img = blockIdx.y;
    const float* __restrict__ sd = img ? g_sorted1 : g_sorted0;
    const unsigned int* bs = img ? g_bs1 : g_bs0;
    float* h = img ? g_h1 : g_h0;
    int b = blockIdx.x;
    int t = threadIdx.x;

    unsigned int sA = bs[b], eA = bs[b + 1];
    unsigned int nA = eA - sA;                       // group b   -> weight (1-d)
    unsigned int sB = (b > 0) ? bs[b - 1] : 0u;
    unsigned int nB = (b > 0) ? (bs[b] - sB) : 0u;   // group b-1 -> weight d
    unsigned int total = nA + nB;
    int ntile = (int)((total + FT - 1) / FT);

    // stage tile 0
    if (t >= 32 && ntile > 0) {
        unsigned int lim = (total < (unsigned int)FT) ? total : (unsigned int)FT;
        #pragma unroll 4
        for (unsigned int j = (unsigned int)(t - 32); j < lim; j += 128u)
            buf[0][j] = (j < nA) ? __fsub_rn(1.0f, sd[sA + j])
                                 : sd[sB + (j - nA)];
    }
    __syncthreads();

    float acc = 0.0f;
    for (int k = 0; k < ntile; k++) {
        int cur = k & 1;
        if (t >= 32) {
            if (k + 1 < ntile) {                     // prefetch next tile
                unsigned int nb = (unsigned int)(k + 1) * FT;
                unsigned int rem = total - nb;
                unsigned int lim = (rem < (unsigned int)FT) ? rem : (unsigned int)FT;
                #pragma unroll 4
                for (unsigned int j = (unsigned int)(t - 32); j < lim; j += 128u) {
                    unsigned int jj = nb + j;
                    buf[cur ^ 1][j] = (jj < nA) ? __fsub_rn(1.0f, sd[sA + jj])
                                                : sd[sB + (jj - nA)];
                }
            }
        } else if (t == 0) {
            unsigned int rem = total - (unsigned int)k * FT;
            if (rem >= (unsigned int)FT) {
                const float4* __restrict__ B4 = (const float4*)buf[cur];
                #pragma unroll 4
                for (int i = 0; i < FT / 4; i++) {
                    float4 v = B4[i];
                    acc = __fadd_rn(acc, v.x);
                    acc = __fadd_rn(acc, v.y);
                    acc = __fadd_rn(acc, v.z);
                    acc = __fadd_rn(acc, v.w);
                }
            } else {
                const float* __restrict__ B = buf[cur];
                for (unsigned int i = 0; i < rem; i++)
                    acc = __fadd_rn(acc, B[i]);
            }
        }
        __syncthreads();
    }
    if (t == 0) h[b] = acc;
}

// ---------------- kernel 6: finalize (single thread, reference op-order) -------
__global__ void k_final(float* __restrict__ out) {
    if (threadIdx.x != 0 || blockIdx.x != 0) return;

    float S0 = 0.0f, S1 = 0.0f;
    for (int t = 0; t < NBIN; t++) S0 = __fadd_rn(S0, g_h0[t]);
    for (int t = 0; t < NBIN; t++) S1 = __fadd_rn(S1, g_h1[t]);

    float d0 = __fadd_rn(S0, EPSF);
    float d1 = __fadd_rn(S1, EPSF);

    float acc = 0.0f;
    for (int t = 0; t < NBIN; t++) {
        float h0n = __fdiv_rn(__fadd_rn(g_h0[t], EPSF), d0);
        float h1n = __fdiv_rn(__fadd_rn(g_h1[t], EPSF), d1);
        float num = __fadd_rn(h1n, EPSF);
        float qi  = __fdiv_rn(num, h1n);
        float qt  = __fdiv_rn(num, h0n);
        float inp = xla_logf(qi);
        float tgt = xla_logf(qt);
        float et  = xla_expf(tgt);
        float term = __fmul_rn(et, __fsub_rn(tgt, inp));
        acc = __fadd_rn(acc, term);
    }
    out[0] = __fdiv_rn(acc, 256.0f);
}

// ---------------- launch ----------------
extern "C" void kernel_launch(void* const* d_in, const int* in_sizes, int n_in,
                              void* d_out, int out_size) {
    const float* img0 = (const float*)d_in[0];
    const float* img1 = (const float*)d_in[1];
    float* out = (float*)d_out;
    int n = in_sizes[0];
    if (n > MAXN) n = MAXN;
    int nchunk = (n + CH - 1) / CH;

    k_init <<<1, 1>>>();
    k_min  <<<1184, 256>>>((const float4*)img0, n >> 2);
    k_stage<<<nchunk, 256>>>((const float4*)img0, (const float4*)img1, n);
    k_scan <<<1, 512>>>(nchunk);
    k_place<<<dim3(nchunk, 2), 256>>>(n);
    k_fold <<<dim3(256, 2), 160>>>();
    k_final<<<1, 32>>>(out);
}

// round 14
// speedup vs baseline: 1.8336x; 1.1501x over previous
#include <cuda_runtime.h>

#define NBIN 256
#define EPSF 1e-10f
#define CH_LG 10
#define CH (1 << CH_LG)                // 1024 elements per chunk
#define MAXN 67108864                  // 4*256^3
#define MAXCHUNK (MAXN / CH)           // 65536
#define FT 4096                        // fold tile (floats)

// ---------------- device scratch (static; no runtime allocation) ----------------
__device__ unsigned int g_min_ord;
__device__ unsigned int g_cnt0[MAXCHUNK * 256];   // [chunk][bin]: counts -> rel prefix
__device__ unsigned int g_cnt1[MAXCHUNK * 256];
__device__ unsigned int g_tot[512];               // per (img,bin) totals
__device__ unsigned int g_bs0[NBIN + 1];          // global group starts
__device__ unsigned int g_bs1[NBIN + 1];
__device__ float g_sx0[MAXN];                     // staged x = (v-hmin)/dh (-1 = drop)
__device__ float g_sx1[MAXN];
__device__ float g_sorted0[MAXN];                 // d values, stably sorted by bin
__device__ float g_sorted1[MAXN];
__device__ float g_h0[NBIN];
__device__ float g_h1[NBIN];

// Order-preserving float<->uint so unsigned atomicMin == float min.
__device__ __forceinline__ unsigned int f2ord(float f) {
    unsigned int u = __float_as_uint(f);
    return (u & 0x80000000u) ? ~u : (u | 0x80000000u);
}
__device__ __forceinline__ float ord2f(unsigned int o) {
    return __uint_as_float((o & 0x80000000u) ? (o & 0x7FFFFFFFu) : ~o);
}

// ---------------- Cephes-style f32 log/exp (XLA:CPU lineage, FMA form) ----------
__device__ __forceinline__ float xla_logf(float x) {
    unsigned int ix = __float_as_uint(x);
    int e = (int)(ix >> 23) - 126;
    float m = __uint_as_float((ix & 0x007FFFFFu) | 0x3F000000u);   // [0.5, 1)
    float ef = (float)e;
    if (m < 0.707106781186547524f) { ef -= 1.0f; m = m + m; }      // exact
    float xm = m - 1.0f;                                           // exact
    float z = __fmul_rn(xm, xm);
    float y = 7.0376836292E-2f;
    y = __fmaf_rn(y, xm, -1.1514610310E-1f);
    y = __fmaf_rn(y, xm,  1.1676998740E-1f);
    y = __fmaf_rn(y, xm, -1.2420140846E-1f);
    y = __fmaf_rn(y, xm,  1.4249322787E-1f);
    y = __fmaf_rn(y, xm, -1.6668057665E-1f);
    y = __fmaf_rn(y, xm,  2.0000714765E-1f);
    y = __fmaf_rn(y, xm, -2.4999993993E-1f);
    y = __fmaf_rn(y, xm,  3.3333331174E-1f);
    y = __fmul_rn(y, xm);
    y = __fmul_rn(y, z);
    y = __fmaf_rn(ef, -2.12194440e-4f, y);
    y = __fmaf_rn(z, -0.5f, y);
    float r = __fadd_rn(xm, y);
    r = __fmaf_rn(ef, 0.693359375f, r);
    return r;
}
__device__ __forceinline__ float xla_expf(float x) {
    x = fminf(x, 88.723164f);
    x = fmaxf(x, -88.723164f);
    float m = floorf(__fmaf_rn(x, 1.44269504088896341f, 0.5f));
    float r = __fmaf_rn(m, -0.693359375f, x);
    r = __fmaf_rn(m, 2.12194440e-4f, r);
    float r2 = __fmul_rn(r, r);
    float p = 1.9875691500E-4f;
    p = __fmaf_rn(p, r, 1.3981999507E-3f);
    p = __fmaf_rn(p, r, 8.3334519073E-3f);
    p = __fmaf_rn(p, r, 4.1665795894E-2f);
    p = __fmaf_rn(p, r, 1.6666665459E-1f);
    p = __fmaf_rn(p, r, 5.0000001201E-1f);
    float y = __fmaf_rn(p, r2, r);
    y = __fadd_rn(y, 1.0f);
    int mi = (int)m;
    return __fmul_rn(y, __uint_as_float((unsigned int)(mi + 127) << 23));
}

// ---------------- kernel 0: reset min ----------------
__global__ void k_init() { g_min_ord = 0xFFFFFFFFu; }

// ---------------- kernel 1: global min of img0 (float4) ----------------
__global__ void k_min(const float4* __restrict__ img, int n4) {
    float m = 3.402823466e38f;
    int stride = gridDim.x * blockDim.x;
    for (int i = blockIdx.x * blockDim.x + threadIdx.x; i < n4; i += stride) {
        float4 v = img[i];
        m = fminf(m, fminf(fminf(v.x, v.y), fminf(v.z, v.w)));
    }
    #pragma unroll
    for (int o = 16; o; o >>= 1) m = fminf(m, __shfl_xor_sync(0xFFFFFFFFu, m, o));
    __shared__ float sm[32];
    int lane = threadIdx.x & 31, w = threadIdx.x >> 5;
    if (lane == 0) sm[w] = m;
    __syncthreads();
    if (w == 0) {
        int nw = (blockDim.x + 31) >> 5;
        m = (lane < nw) ? sm[lane] : 3.402823466e38f;
        #pragma unroll
        for (int o = 16; o; o >>= 1) m = fminf(m, __shfl_xor_sync(0xFFFFFFFFu, m, o));
        if (lane == 0) atomicMin(&g_min_ord, f2ord(m));
    }
}

// ---------------- binning math (bit-exact vs reference) ----------------
// Stores x = (v - hmin)/dh (IEEE RN div) when kept; floor/d recomputed later
// from the SAME bits. x >= 0 for all kept values; -1 sentinel otherwise.
__device__ __forceinline__ void stage_one(float v, float hmin, float dh,
                                          int& idx, float& xout) {
    if (v >= hmin && v <= 0.0f) {
        float x = __fdiv_rn(v - hmin, dh);
        idx = (int)floorf(x);
        xout = x;
    } else {
        idx = 0;
        xout = -1.0f;
    }
}

// ---------------- kernel 2: stage (bin once) + per-(chunk,bin) counts ----------
__global__ void k_stage(const float4* __restrict__ i0, const float4* __restrict__ i1,
                        int n) {
    __shared__ unsigned int sc0[256], sc1[256];
    int t = threadIdx.x;
    sc0[t] = 0u; sc1[t] = 0u;
    __syncthreads();

    float hmin = ord2f(g_min_ord);
    float dh   = __fdiv_rn(0.0f - hmin, 255.0f);
    int chunk = blockIdx.x;
    int i4 = (chunk << (CH_LG - 2)) + t;           // float4 index

    if (i4 * 4 < n) {
        float4 a = i0[i4];
        float4 b = i1[i4];
        int ia0, ia1, ia2, ia3, ib0, ib1, ib2, ib3;
        float xa0, xa1, xa2, xa3, xb0, xb1, xb2, xb3;
        stage_one(a.x, hmin, dh, ia0, xa0);
        stage_one(a.y, hmin, dh, ia1, xa1);
        stage_one(a.z, hmin, dh, ia2, xa2);
        stage_one(a.w, hmin, dh, ia3, xa3);
        stage_one(b.x, hmin, dh, ib0, xb0);
        stage_one(b.y, hmin, dh, ib1, xb1);
        stage_one(b.z, hmin, dh, ib2, xb2);
        stage_one(b.w, hmin, dh, ib3, xb3);
        if (xa0 >= 0.0f) atomicAdd(&sc0[ia0], 1u);
        if (xa1 >= 0.0f) atomicAdd(&sc0[ia1], 1u);
        if (xa2 >= 0.0f) atomicAdd(&sc0[ia2], 1u);
        if (xa3 >= 0.0f) atomicAdd(&sc0[ia3], 1u);
        if (xb0 >= 0.0f) atomicAdd(&sc1[ib0], 1u);
        if (xb1 >= 0.0f) atomicAdd(&sc1[ib1], 1u);
        if (xb2 >= 0.0f) atomicAdd(&sc1[ib2], 1u);
        if (xb3 >= 0.0f) atomicAdd(&sc1[ib3], 1u);
        ((float4*)g_sx0)[i4] = make_float4(xa0, xa1, xa2, xa3);
        ((float4*)g_sx1)[i4] = make_float4(xb0, xb1, xb2, xb3);
    }
    __syncthreads();
    g_cnt0[chunk * 256 + t] = sc0[t];              // coalesced [chunk][bin]
    g_cnt1[chunk * 256 + t] = sc1[t];
}

// ---------------- kernel 3a: per-bin prefix over chunks (parallel) -------------
// grid (8, 2), 32 threads: warp g owns bins 32g..32g+31 for image blockIdx.y.
// Loads/stores are 32 consecutive u32 = coalesced. Single fused pass:
// rewrite counts -> within-bin exclusive prefix; final run = bin total.
__global__ void k_scanA(int nchunk) {
    int lane = threadIdx.x;
    int bin  = (blockIdx.x << 5) + lane;
    int img  = blockIdx.y;
    unsigned int* __restrict__ cnt = img ? g_cnt1 : g_cnt0;

    unsigned int run = 0;
    #pragma unroll 8
    for (int c = 0; c < nchunk; c++) {
        unsigned int v = cnt[c * 256 + bin];
        cnt[c * 256 + bin] = run;
        run += v;
    }
    g_tot[(img << 8) + bin] = run;
}

// ---------------- kernel 3b: 256-bin exclusive scan -> group starts ------------
__global__ void k_scanB() {
    __shared__ unsigned int s[512];
    int t = threadIdx.x;           // 512 threads: img = t>>8, bin = t&255
    s[t] = g_tot[t];
    __syncthreads();
    if ((t & 255) == 0) {
        int img = t >> 8;
        unsigned int* bs = img ? g_bs1 : g_bs0;
        unsigned int run = 0;
        for (int j = 0; j < 256; j++) {
            unsigned int v = s[(img << 8) + j];
            bs[j] = run;
            run += v;
        }
        bs[256] = run;
    }
}

// ---------------- kernel 4: stable placement, 3 barriers per 1024 elems --------
// grid (nchunk, 2), 256 threads, 4 elems/thread. Segment = (wave, warp):
// element order = (wave, warp, lane) lexicographic => stability preserved.
__global__ void k_place(int n) {
    __shared__ unsigned short s_cnt[32][256];      // [segment][bin] counts->starts
    __shared__ unsigned int s_gs[256];             // global starts for this chunk

    int img = blockIdx.y;
    const float* __restrict__ sxv = img ? g_sx1 : g_sx0;
    const unsigned int* __restrict__ cnt = img ? g_cnt1 : g_cnt0;
    const unsigned int* __restrict__ bs = img ? g_bs1 : g_bs0;
    float* __restrict__ outp = img ? g_sorted1 : g_sorted0;

    int chunk = blockIdx.x;
    int base  = chunk << CH_LG;
    int t     = threadIdx.x;
    int lane  = t & 31, w = t >> 5;

    // zero count table (16KB = 4096 u32)
    #pragma unroll
    for (int k = 0; k < 16; k++)
        ((unsigned int*)s_cnt)[t + (k << 8)] = 0u;
    s_gs[t] = bs[t] + cnt[chunk * 256 + t];        // absolute start, coalesced
    __syncthreads();

    // phase 1: match-based per-(segment,bin) counts; ranks/d kept in registers
    int   idxs[4];
    int   ranks[4];
    float ds[4];
    #pragma unroll
    for (int wv = 0; wv < 4; wv++) {
        int i = base + (wv << 8) + t;
        float x = (i < n) ? sxv[i] : -1.0f;
        bool keep = (x >= 0.0f);
        float fi = floorf(x);
        int idx = keep ? (int)fi : 0;
        float d = x - fi;                           // exact, same bits as stage
        unsigned int key = keep ? (unsigned int)idx : (0x1000u + (unsigned int)lane);
        unsigned int mask = __match_any_sync(0xFFFFFFFFu, key);
        int rank = __popc(mask & ((1u << lane) - 1u));
        int seg = (wv << 3) + w;
        if (keep && rank == 0)
            s_cnt[seg][idx] = (unsigned short)__popc(mask);
        idxs[wv] = idx; ranks[wv] = rank; ds[wv] = keep ? d : -1.0f;
    }
    __syncthreads();

    // phase 2: thread t owns bin t; exclusive prefix over 32 segments in regs
    {
        unsigned int c[32];
        #pragma unroll
        for (int s = 0; s < 32; s++) c[s] = s_cnt[s][t];
        unsigned int run = 0;
        #pragma unroll
        for (int s = 0; s < 32; s++) { unsigned int v = c[s]; c[s] = run; run += v; }
        #pragma unroll
        for (int s = 0; s < 32; s++) s_cnt[s][t] = (unsigned short)c[s];
    }
    __syncthreads();

    // phase 3: write out
    #pragma unroll
    for (int wv = 0; wv < 4; wv++) {
        if (ds[wv] >= 0.0f) {
            int seg = (wv << 3) + w;
            int idx = idxs[wv];
            unsigned int off = s_gs[idx] + (unsigned int)s_cnt[seg][idx]
                             + (unsigned int)ranks[wv];
            outp[off] = ds[wv];
        }
    }
}

// ---------------- kernel 5: exact sequential f32 fold, staged through smem -----
// grid (256, 2), 160 threads. Loaders (t>=32) stage double-buffered tiles with
// the weight transform applied (same __fsub_rn bits). Folder = warp0 lane0,
// compile-time float4 loop: 4 cyc/elem dependency chain, bit-identical order.
__global__ void k_fold() {
    __shared__ __align__(16) float buf[2][FT];
    int img = blockIdx.y;
    const float* __restrict__ sd = img ? g_sorted1 : g_sorted0;
    const unsigned int* bs = img ? g_bs1 : g_bs0;
    float* h = img ? g_h1 : g_h0;
    int b = blockIdx.x;
    int t = threadIdx.x;

    unsigned int sA = bs[b], eA = bs[b + 1];
    unsigned int nA = eA - sA;                       // group b   -> weight (1-d)
    unsigned int sB = (b > 0) ? bs[b - 1] : 0u;
    unsigned int nB = (b > 0) ? (bs[b] - sB) : 0u;   // group b-1 -> weight d
    unsigned int total = nA + nB;
    int ntile = (int)((total + FT - 1) / FT);

    // stage tile 0
    if (t >= 32 && ntile > 0) {
        unsigned int lim = (total < (unsigned int)FT) ? total : (unsigned int)FT;
        #pragma unroll 4
        for (unsigned int j = (unsigned int)(t - 32); j < lim; j += 128u)
            buf[0][j] = (j < nA) ? __fsub_rn(1.0f, sd[sA + j])
                                 : sd[sB + (j - nA)];
    }
    __syncthreads();

    float acc = 0.0f;
    for (int k = 0; k < ntile; k++) {
        int cur = k & 1;
        if (t >= 32) {
            if (k + 1 < ntile) {                     // prefetch next tile
                unsigned int nb = (unsigned int)(k + 1) * FT;
                unsigned int rem = total - nb;
                unsigned int lim = (rem < (unsigned int)FT) ? rem : (unsigned int)FT;
                #pragma unroll 4
                for (unsigned int j = (unsigned int)(t - 32); j < lim; j += 128u) {
                    unsigned int jj = nb + j;
                    buf[cur ^ 1][j] = (jj < nA) ? __fsub_rn(1.0f, sd[sA + jj])
                                                : sd[sB + (jj - nA)];
                }
            }
        } else if (t == 0) {
            unsigned int rem = total - (unsigned int)k * FT;
            if (rem >= (unsigned int)FT) {
                const float4* __restrict__ B4 = (const float4*)buf[cur];
                #pragma unroll 4
                for (int i = 0; i < FT / 4; i++) {
                    float4 v = B4[i];
                    acc = __fadd_rn(acc, v.x);
                    acc = __fadd_rn(acc, v.y);
                    acc = __fadd_rn(acc, v.z);
                    acc = __fadd_rn(acc, v.w);
                }
            } else {
                const float* __restrict__ B = buf[cur];
                for (unsigned int i = 0; i < rem; i++)
                    acc = __fadd_rn(acc, B[i]);
            }
        }
        __syncthreads();
    }
    if (t == 0) h[b] = acc;
}

// ---------------- kernel 6: finalize (single thread, reference op-order) -------
__global__ void k_final(float* __restrict__ out) {
    if (threadIdx.x != 0 || blockIdx.x != 0) return;

    float S0 = 0.0f, S1 = 0.0f;
    for (int t = 0; t < NBIN; t++) S0 = __fadd_rn(S0, g_h0[t]);
    for (int t = 0; t < NBIN; t++) S1 = __fadd_rn(S1, g_h1[t]);

    float d0 = __fadd_rn(S0, EPSF);
    float d1 = __fadd_rn(S1, EPSF);

    float acc = 0.0f;
    for (int t = 0; t < NBIN; t++) {
        float h0n = __fdiv_rn(__fadd_rn(g_h0[t], EPSF), d0);
        float h1n = __fdiv_rn(__fadd_rn(g_h1[t], EPSF), d1);
        float num = __fadd_rn(h1n, EPSF);
        float qi  = __fdiv_rn(num, h1n);
        float qt  = __fdiv_rn(num, h0n);
        float inp = xla_logf(qi);
        float tgt = xla_logf(qt);
        float et  = xla_expf(tgt);
        float term = __fmul_rn(et, __fsub_rn(tgt, inp));
        acc = __fadd_rn(acc, term);
    }
    out[0] = __fdiv_rn(acc, 256.0f);
}

// ---------------- launch ----------------
extern "C" void kernel_launch(void* const* d_in, const int* in_sizes, int n_in,
                              void* d_out, int out_size) {
    const float* img0 = (const float*)d_in[0];
    const float* img1 = (const float*)d_in[1];
    float* out = (float*)d_out;
    int n = in_sizes[0];
    if (n > MAXN) n = MAXN;
    int nchunk = (n + CH - 1) / CH;

    k_init <<<1, 1>>>();
    k_min  <<<1184, 256>>>((const float4*)img0, n >> 2);
    k_stage<<<nchunk, 256>>>((const float4*)img0, (const float4*)img1, n);
    k_scanA<<<dim3(8, 2), 32>>>(nchunk);
    k_scanB<<<1, 512>>>();
    k_place<<<dim3(nchunk, 2), 256>>>(n);
    k_fold <<<dim3(256, 2), 160>>>();
    k_final<<<1, 32>>>(out);
}

// round 15
// speedup vs baseline: 4.5683x; 2.4915x over previous
#include <cuda_runtime.h>

#define NBIN 256
#define EPSF 1e-10f
#define CH_LG 10
#define CH (1 << CH_LG)                // 1024 elements per chunk
#define MAXN 67108864                  // 4*256^3
#define MAXCHUNK (MAXN / CH)           // 65536
#define MAXSEG (MAXCHUNK / 256)        // 256 segments of 256 chunks
#define FT 4096                        // fold tile (floats)

// ---------------- device scratch (static; no runtime allocation) ----------------
__device__ unsigned int g_min_ord;
__device__ unsigned int g_cnt0[MAXCHUNK * 256];   // [chunk][bin]: counts -> in-seg prefix
__device__ unsigned int g_cnt1[MAXCHUNK * 256];
__device__ unsigned int g_seg0[MAXSEG * 256];     // [seg][bin]: totals -> seg offsets
__device__ unsigned int g_seg1[MAXSEG * 256];
__device__ unsigned int g_tot[512];               // per (img,bin) totals
__device__ unsigned int g_bs0[NBIN + 1];          // global group starts
__device__ unsigned int g_bs1[NBIN + 1];
__device__ float g_sx0[MAXN];                     // staged x = (v-hmin)/dh (-1 = drop)
__device__ float g_sx1[MAXN];
__device__ float g_sorted0[MAXN];                 // d values, stably sorted by bin
__device__ float g_sorted1[MAXN];
__device__ float g_h0[NBIN];
__device__ float g_h1[NBIN];

// Order-preserving float<->uint so unsigned atomicMin == float min.
__device__ __forceinline__ unsigned int f2ord(float f) {
    unsigned int u = __float_as_uint(f);
    return (u & 0x80000000u) ? ~u : (u | 0x80000000u);
}
__device__ __forceinline__ float ord2f(unsigned int o) {
    return __uint_as_float((o & 0x80000000u) ? (o & 0x7FFFFFFFu) : ~o);
}

// ---------------- Cephes-style f32 log/exp (XLA:CPU lineage, FMA form) ----------
__device__ __forceinline__ float xla_logf(float x) {
    unsigned int ix = __float_as_uint(x);
    int e = (int)(ix >> 23) - 126;
    float m = __uint_as_float((ix & 0x007FFFFFu) | 0x3F000000u);   // [0.5, 1)
    float ef = (float)e;
    if (m < 0.707106781186547524f) { ef -= 1.0f; m = m + m; }      // exact
    float xm = m - 1.0f;                                           // exact
    float z = __fmul_rn(xm, xm);
    float y = 7.0376836292E-2f;
    y = __fmaf_rn(y, xm, -1.1514610310E-1f);
    y = __fmaf_rn(y, xm,  1.1676998740E-1f);
    y = __fmaf_rn(y, xm, -1.2420140846E-1f);
    y = __fmaf_rn(y, xm,  1.4249322787E-1f);
    y = __fmaf_rn(y, xm, -1.6668057665E-1f);
    y = __fmaf_rn(y, xm,  2.0000714765E-1f);
    y = __fmaf_rn(y, xm, -2.4999993993E-1f);
    y = __fmaf_rn(y, xm,  3.3333331174E-1f);
    y = __fmul_rn(y, xm);
    y = __fmul_rn(y, z);
    y = __fmaf_rn(ef, -2.12194440e-4f, y);
    y = __fmaf_rn(z, -0.5f, y);
    float r = __fadd_rn(xm, y);
    r = __fmaf_rn(ef, 0.693359375f, r);
    return r;
}
__device__ __forceinline__ float xla_expf(float x) {
    x = fminf(x, 88.723164f);
    x = fmaxf(x, -88.723164f);
    float m = floorf(__fmaf_rn(x, 1.44269504088896341f, 0.5f));
    float r = __fmaf_rn(m, -0.693359375f, x);
    r = __fmaf_rn(m, 2.12194440e-4f, r);
    float r2 = __fmul_rn(r, r);
    float p = 1.9875691500E-4f;
    p = __fmaf_rn(p, r, 1.3981999507E-3f);
    p = __fmaf_rn(p, r, 8.3334519073E-3f);
    p = __fmaf_rn(p, r, 4.1665795894E-2f);
    p = __fmaf_rn(p, r, 1.6666665459E-1f);
    p = __fmaf_rn(p, r, 5.0000001201E-1f);
    float y = __fmaf_rn(p, r2, r);
    y = __fadd_rn(y, 1.0f);
    int mi = (int)m;
    return __fmul_rn(y, __uint_as_float((unsigned int)(mi + 127) << 23));
}

// ---------------- kernel 0: reset min ----------------
__global__ void k_init() { g_min_ord = 0xFFFFFFFFu; }

// ---------------- kernel 1: global min of img0 (float4) ----------------
__global__ void k_min(const float4* __restrict__ img, int n4) {
    float m = 3.402823466e38f;
    int stride = gridDim.x * blockDim.x;
    for (int i = blockIdx.x * blockDim.x + threadIdx.x; i < n4; i += stride) {
        float4 v = img[i];
        m = fminf(m, fminf(fminf(v.x, v.y), fminf(v.z, v.w)));
    }
    #pragma unroll
    for (int o = 16; o; o >>= 1) m = fminf(m, __shfl_xor_sync(0xFFFFFFFFu, m, o));
    __shared__ float sm[32];
    int lane = threadIdx.x & 31, w = threadIdx.x >> 5;
    if (lane == 0) sm[w] = m;
    __syncthreads();
    if (w == 0) {
        int nw = (blockDim.x + 31) >> 5;
        m = (lane < nw) ? sm[lane] : 3.402823466e38f;
        #pragma unroll
        for (int o = 16; o; o >>= 1) m = fminf(m, __shfl_xor_sync(0xFFFFFFFFu, m, o));
        if (lane == 0) atomicMin(&g_min_ord, f2ord(m));
    }
}

// ---------------- binning math (bit-exact vs reference) ----------------
__device__ __forceinline__ void stage_one(float v, float hmin, float dh,
                                          int& idx, float& xout) {
    if (v >= hmin && v <= 0.0f) {
        float x = __fdiv_rn(v - hmin, dh);
        idx = (int)floorf(x);
        xout = x;
    } else {
        idx = 0;
        xout = -1.0f;
    }
}

// ---------------- kernel 2: stage (bin once) + per-(chunk,bin) counts ----------
__global__ void k_stage(const float4* __restrict__ i0, const float4* __restrict__ i1,
                        int n) {
    __shared__ unsigned int sc0[256], sc1[256];
    int t = threadIdx.x;
    sc0[t] = 0u; sc1[t] = 0u;
    __syncthreads();

    float hmin = ord2f(g_min_ord);
    float dh   = __fdiv_rn(0.0f - hmin, 255.0f);
    int chunk = blockIdx.x;
    int i4 = (chunk << (CH_LG - 2)) + t;           // float4 index

    if (i4 * 4 < n) {
        float4 a = i0[i4];
        float4 b = i1[i4];
        int ia0, ia1, ia2, ia3, ib0, ib1, ib2, ib3;
        float xa0, xa1, xa2, xa3, xb0, xb1, xb2, xb3;
        stage_one(a.x, hmin, dh, ia0, xa0);
        stage_one(a.y, hmin, dh, ia1, xa1);
        stage_one(a.z, hmin, dh, ia2, xa2);
        stage_one(a.w, hmin, dh, ia3, xa3);
        stage_one(b.x, hmin, dh, ib0, xb0);
        stage_one(b.y, hmin, dh, ib1, xb1);
        stage_one(b.z, hmin, dh, ib2, xb2);
        stage_one(b.w, hmin, dh, ib3, xb3);
        if (xa0 >= 0.0f) atomicAdd(&sc0[ia0], 1u);
        if (xa1 >= 0.0f) atomicAdd(&sc0[ia1], 1u);
        if (xa2 >= 0.0f) atomicAdd(&sc0[ia2], 1u);
        if (xa3 >= 0.0f) atomicAdd(&sc0[ia3], 1u);
        if (xb0 >= 0.0f) atomicAdd(&sc1[ib0], 1u);
        if (xb1 >= 0.0f) atomicAdd(&sc1[ib1], 1u);
        if (xb2 >= 0.0f) atomicAdd(&sc1[ib2], 1u);
        if (xb3 >= 0.0f) atomicAdd(&sc1[ib3], 1u);
        ((float4*)g_sx0)[i4] = make_float4(xa0, xa1, xa2, xa3);
        ((float4*)g_sx1)[i4] = make_float4(xb0, xb1, xb2, xb3);
    }
    __syncthreads();
    g_cnt0[chunk * 256 + t] = sc0[t];              // coalesced [chunk][bin]
    g_cnt1[chunk * 256 + t] = sc1[t];
}

// ---------------- kernel 3a1: per-segment, per-bin prefix over chunks ----------
// grid (nseg, 2), 256 threads: thread t = bin t; segment = 256 chunks.
// All loads/stores coalesced (256 consecutive u32 per iteration).
__global__ void k_scanA1(int nchunk) {
    int img = blockIdx.y;
    unsigned int* __restrict__ cnt = img ? g_cnt1 : g_cnt0;
    unsigned int* __restrict__ seg = img ? g_seg1 : g_seg0;
    int s = blockIdx.x;
    int t = threadIdx.x;

    int c0 = s << 8;
    int c1 = c0 + 256; if (c1 > nchunk) c1 = nchunk;
    unsigned int run = 0;
    for (int c = c0; c < c1; c++) {
        unsigned int v = cnt[c * 256 + t];
        cnt[c * 256 + t] = run;                    // in-segment exclusive prefix
        run += v;
    }
    seg[s * 256 + t] = run;                        // segment total
}

// ---------------- kernel 3a2: per-bin scan over segment totals -----------------
// grid (8, 2), 32 threads: warp owns 32 bins; 256 coalesced iterations.
__global__ void k_scanA2(int nseg) {
    int lane = threadIdx.x;
    int bin  = (blockIdx.x << 5) + lane;
    int img  = blockIdx.y;
    unsigned int* __restrict__ seg = img ? g_seg1 : g_seg0;

    unsigned int run = 0;
    #pragma unroll 8
    for (int s = 0; s < nseg; s++) {
        unsigned int v = seg[s * 256 + bin];
        seg[s * 256 + bin] = run;                  // segment offset within bin
        run += v;
    }
    g_tot[(img << 8) + bin] = run;
}

// ---------------- kernel 3b: 256-bin exclusive scan -> group starts ------------
__global__ void k_scanB() {
    __shared__ unsigned int s[512];
    int t = threadIdx.x;           // 512 threads: img = t>>8, bin = t&255
    s[t] = g_tot[t];
    __syncthreads();
    if ((t & 255) == 0) {
        int img = t >> 8;
        unsigned int* bs = img ? g_bs1 : g_bs0;
        unsigned int run = 0;
        for (int j = 0; j < 256; j++) {
            unsigned int v = s[(img << 8) + j];
            bs[j] = run;
            run += v;
        }
        bs[256] = run;
    }
}

// ---------------- kernel 4: stable placement, 3 barriers per 1024 elems --------
__global__ void k_place(int n) {
    __shared__ unsigned short s_cnt[32][256];      // [segment][bin] counts->starts
    __shared__ unsigned int s_gs[256];             // absolute starts for this chunk

    int img = blockIdx.y;
    const float* __restrict__ sxv = img ? g_sx1 : g_sx0;
    const unsigned int* __restrict__ cnt = img ? g_cnt1 : g_cnt0;
    const unsigned int* __restrict__ seg = img ? g_seg1 : g_seg0;
    const unsigned int* __restrict__ bs = img ? g_bs1 : g_bs0;
    float* __restrict__ outp = img ? g_sorted1 : g_sorted0;

    int chunk = blockIdx.x;
    int base  = chunk << CH_LG;
    int t     = threadIdx.x;
    int lane  = t & 31, w = t >> 5;

    #pragma unroll
    for (int k = 0; k < 16; k++)
        ((unsigned int*)s_cnt)[t + (k << 8)] = 0u;
    // absolute start = bin start + segment offset + in-segment chunk prefix
    s_gs[t] = bs[t] + seg[(chunk >> 8) * 256 + t] + cnt[chunk * 256 + t];
    __syncthreads();

    int   idxs[4];
    int   ranks[4];
    float ds[4];
    #pragma unroll
    for (int wv = 0; wv < 4; wv++) {
        int i = base + (wv << 8) + t;
        float x = (i < n) ? sxv[i] : -1.0f;
        bool keep = (x >= 0.0f);
        float fi = floorf(x);
        int idx = keep ? (int)fi : 0;
        float d = x - fi;                           // exact, same bits as stage
        unsigned int key = keep ? (unsigned int)idx : (0x1000u + (unsigned int)lane);
        unsigned int mask = __match_any_sync(0xFFFFFFFFu, key);
        int rank = __popc(mask & ((1u << lane) - 1u));
        int sg = (wv << 3) + w;
        if (keep && rank == 0)
            s_cnt[sg][idx] = (unsigned short)__popc(mask);
        idxs[wv] = idx; ranks[wv] = rank; ds[wv] = keep ? d : -1.0f;
    }
    __syncthreads();

    {
        unsigned int c[32];
        #pragma unroll
        for (int s2 = 0; s2 < 32; s2++) c[s2] = s_cnt[s2][t];
        unsigned int run = 0;
        #pragma unroll
        for (int s2 = 0; s2 < 32; s2++) { unsigned int v = c[s2]; c[s2] = run; run += v; }
        #pragma unroll
        for (int s2 = 0; s2 < 32; s2++) s_cnt[s2][t] = (unsigned short)c[s2];
    }
    __syncthreads();

    #pragma unroll
    for (int wv = 0; wv < 4; wv++) {
        if (ds[wv] >= 0.0f) {
            int sg = (wv << 3) + w;
            int idx = idxs[wv];
            unsigned int off = s_gs[idx] + (unsigned int)s_cnt[sg][idx]
                             + (unsigned int)ranks[wv];
            outp[off] = ds[wv];
        }
    }
}

// ---------------- kernel 5: exact sequential f32 fold, software-pipelined ------
// grid (256, 2), 160 threads. Loaders (t>=32) stage double-buffered tiles with
// the weight transform applied. Folder = warp0 lane0: explicit register double
// buffering — load batch k+1 (8x LDS.128) while running batch k's 32-FADD
// chain. Element order identical; the trailing redundant load of batch 0 is
// never accumulated.
__global__ void k_fold() {
    __shared__ __align__(16) float buf[2][FT];
    int img = blockIdx.y;
    const float* __restrict__ sd = img ? g_sorted1 : g_sorted0;
    const unsigned int* bs = img ? g_bs1 : g_bs0;
    float* h = img ? g_h1 : g_h0;
    int b = blockIdx.x;
    int t = threadIdx.x;

    unsigned int sA = bs[b], eA = bs[b + 1];
    unsigned int nA = eA - sA;                       // group b   -> weight (1-d)
    unsigned int sB = (b > 0) ? bs[b - 1] : 0u;
    unsigned int nB = (b > 0) ? (bs[b] - sB) : 0u;   // group b-1 -> weight d
    unsigned int total = nA + nB;
    int ntile = (int)((total + FT - 1) / FT);

    if (t >= 32 && ntile > 0) {
        unsigned int lim = (total < (unsigned int)FT) ? total : (unsigned int)FT;
        #pragma unroll 4
        for (unsigned int j = (unsigned int)(t - 32); j < lim; j += 128u)
            buf[0][j] = (j < nA) ? __fsub_rn(1.0f, sd[sA + j])
                                 : sd[sB + (j - nA)];
    }
    __syncthreads();

    float acc = 0.0f;
    for (int k = 0; k < ntile; k++) {
        int cur = k & 1;
        if (t >= 32) {
            if (k + 1 < ntile) {                     // prefetch next tile
                unsigned int nb = (unsigned int)(k + 1) * FT;
                unsigned int rem = total - nb;
                unsigned int lim = (rem < (unsigned int)FT) ? rem : (unsigned int)FT;
                #pragma unroll 4
                for (unsigned int j = (unsigned int)(t - 32); j < lim; j += 128u) {
                    unsigned int jj = nb + j;
                    buf[cur ^ 1][j] = (jj < nA) ? __fsub_rn(1.0f, sd[sA + jj])
                                                : sd[sB + (jj - nA)];
                }
            }
        } else if (t == 0) {
            unsigned int rem = total - (unsigned int)k * FT;
            if (rem >= (unsigned int)FT) {
                const float4* __restrict__ B4 = (const float4*)buf[cur];
                float4 ra[8], rb[8];
                #pragma unroll
                for (int u = 0; u < 8; u++) ra[u] = B4[u];
                #pragma unroll 1
                for (int g = 0; g < 128; g += 2) {
                    int n1 = (g + 1) << 3;
                    #pragma unroll
                    for (int u = 0; u < 8; u++) rb[u] = B4[n1 + u];
                    #pragma unroll
                    for (int u = 0; u < 8; u++) {
                        acc = __fadd_rn(acc, ra[u].x);
                        acc = __fadd_rn(acc, ra[u].y);
                        acc = __fadd_rn(acc, ra[u].z);
                        acc = __fadd_rn(acc, ra[u].w);
                    }
                    int n2 = ((g + 2) < 128 ? (g + 2) : 0) << 3;  // dummy at end
                    #pragma unroll
                    for (int u = 0; u < 8; u++) ra[u] = B4[n2 + u];
                    #pragma unroll
                    for (int u = 0; u < 8; u++) {
                        acc = __fadd_rn(acc, rb[u].x);
                        acc = __fadd_rn(acc, rb[u].y);
                        acc = __fadd_rn(acc, rb[u].z);
                        acc = __fadd_rn(acc, rb[u].w);
                    }
                }
            } else {
                const float* __restrict__ B = buf[cur];
                for (unsigned int i = 0; i < rem; i++)
                    acc = __fadd_rn(acc, B[i]);
            }
        }
        __syncthreads();
    }
    if (t == 0) h[b] = acc;
}

// ---------------- kernel 6: finalize (single thread, reference op-order) -------
__global__ void k_final(float* __restrict__ out) {
    if (threadIdx.x != 0 || blockIdx.x != 0) return;

    float S0 = 0.0f, S1 = 0.0f;
    for (int t = 0; t < NBIN; t++) S0 = __fadd_rn(S0, g_h0[t]);
    for (int t = 0; t < NBIN; t++) S1 = __fadd_rn(S1, g_h1[t]);

    float d0 = __fadd_rn(S0, EPSF);
    float d1 = __fadd_rn(S1, EPSF);

    float acc = 0.0f;
    for (int t = 0; t < NBIN; t++) {
        float h0n = __fdiv_rn(__fadd_rn(g_h0[t], EPSF), d0);
        float h1n = __fdiv_rn(__fadd_rn(g_h1[t], EPSF), d1);
        float num = __fadd_rn(h1n, EPSF);
        float qi  = __fdiv_rn(num, h1n);
        float qt  = __fdiv_rn(num, h0n);
        float inp = xla_logf(qi);
        float tgt = xla_logf(qt);
        float et  = xla_expf(tgt);
        float term = __fmul_rn(et, __fsub_rn(tgt, inp));
        acc = __fadd_rn(acc, term);
    }
    out[0] = __fdiv_rn(acc, 256.0f);
}

// ---------------- launch ----------------
extern "C" void kernel_launch(void* const* d_in, const int* in_sizes, int n_in,
                              void* d_out, int out_size) {
    const float* img0 = (const float*)d_in[0];
    const float* img1 = (const float*)d_in[1];
    float* out = (float*)d_out;
    int n = in_sizes[0];
    if (n > MAXN) n = MAXN;
    int nchunk = (n + CH - 1) / CH;
    int nseg = (nchunk + 255) >> 8;

    k_init  <<<1, 1>>>();
    k_min   <<<1184, 256>>>((const float4*)img0, n >> 2);
    k_stage <<<nchunk, 256>>>((const float4*)img0, (const float4*)img1, n);
    k_scanA1<<<dim3(nseg, 2), 256>>>(nchunk);
    k_scanA2<<<dim3(8, 2), 32>>>(nseg);
    k_scanB <<<1, 512>>>();
    k_place <<<dim3(nchunk, 2), 256>>>(n);
    k_fold  <<<dim3(256, 2), 160>>>();
    k_final <<<1, 32>>>(out);
}

// round 16
// speedup vs baseline: 4.8607x; 1.0640x over previous
#include <cuda_runtime.h>

#define NBIN 256
#define EPSF 1e-10f
#define CH_LG 10
#define CH (1 << CH_LG)                // 1024 elements per chunk
#define MAXN 67108864                  // 4*256^3
#define MAXCHUNK (MAXN / CH)           // 65536
#define MAXSEG (MAXCHUNK / 256)        // 256 segments of 256 chunks
#define FT 4096                        // fold tile (floats)

// ---------------- device scratch (static; no runtime allocation) ----------------
__device__ unsigned int g_min_ord;
__device__ unsigned int g_cnt0[MAXCHUNK * 256];   // [chunk][bin]: counts -> in-seg prefix
__device__ unsigned int g_cnt1[MAXCHUNK * 256];
__device__ unsigned int g_seg0[MAXSEG * 256];     // [seg][bin]: totals -> seg offsets
__device__ unsigned int g_seg1[MAXSEG * 256];
__device__ unsigned int g_tot[512];               // per (img,bin) totals
__device__ unsigned int g_bs0[NBIN + 1];          // global group starts
__device__ unsigned int g_bs1[NBIN + 1];
__device__ float g_sx0[MAXN];                     // staged x = (v-hmin)/dh (-1 = drop)
__device__ float g_sx1[MAXN];
__device__ float g_sorted0[MAXN];                 // d values, stably sorted by bin
__device__ float g_sorted1[MAXN];
__device__ float g_h0[NBIN];
__device__ float g_h1[NBIN];

// Order-preserving float<->uint so unsigned atomicMin == float min.
__device__ __forceinline__ unsigned int f2ord(float f) {
    unsigned int u = __float_as_uint(f);
    return (u & 0x80000000u) ? ~u : (u | 0x80000000u);
}
__device__ __forceinline__ float ord2f(unsigned int o) {
    return __uint_as_float((o & 0x80000000u) ? (o & 0x7FFFFFFFu) : ~o);
}

// ---------------- Cephes-style f32 log/exp (XLA:CPU lineage, FMA form) ----------
__device__ __forceinline__ float xla_logf(float x) {
    unsigned int ix = __float_as_uint(x);
    int e = (int)(ix >> 23) - 126;
    float m = __uint_as_float((ix & 0x007FFFFFu) | 0x3F000000u);   // [0.5, 1)
    float ef = (float)e;
    if (m < 0.707106781186547524f) { ef -= 1.0f; m = m + m; }      // exact
    float xm = m - 1.0f;                                           // exact
    float z = __fmul_rn(xm, xm);
    float y = 7.0376836292E-2f;
    y = __fmaf_rn(y, xm, -1.1514610310E-1f);
    y = __fmaf_rn(y, xm,  1.1676998740E-1f);
    y = __fmaf_rn(y, xm, -1.2420140846E-1f);
    y = __fmaf_rn(y, xm,  1.4249322787E-1f);
    y = __fmaf_rn(y, xm, -1.6668057665E-1f);
    y = __fmaf_rn(y, xm,  2.0000714765E-1f);
    y = __fmaf_rn(y, xm, -2.4999993993E-1f);
    y = __fmaf_rn(y, xm,  3.3333331174E-1f);
    y = __fmul_rn(y, xm);
    y = __fmul_rn(y, z);
    y = __fmaf_rn(ef, -2.12194440e-4f, y);
    y = __fmaf_rn(z, -0.5f, y);
    float r = __fadd_rn(xm, y);
    r = __fmaf_rn(ef, 0.693359375f, r);
    return r;
}
__device__ __forceinline__ float xla_expf(float x) {
    x = fminf(x, 88.723164f);
    x = fmaxf(x, -88.723164f);
    float m = floorf(__fmaf_rn(x, 1.44269504088896341f, 0.5f));
    float r = __fmaf_rn(m, -0.693359375f, x);
    r = __fmaf_rn(m, 2.12194440e-4f, r);
    float r2 = __fmul_rn(r, r);
    float p = 1.9875691500E-4f;
    p = __fmaf_rn(p, r, 1.3981999507E-3f);
    p = __fmaf_rn(p, r, 8.3334519073E-3f);
    p = __fmaf_rn(p, r, 4.1665795894E-2f);
    p = __fmaf_rn(p, r, 1.6666665459E-1f);
    p = __fmaf_rn(p, r, 5.0000001201E-1f);
    float y = __fmaf_rn(p, r2, r);
    y = __fadd_rn(y, 1.0f);
    int mi = (int)m;
    return __fmul_rn(y, __uint_as_float((unsigned int)(mi + 127) << 23));
}

// ---------------- kernel 0: reset min ----------------
__global__ void k_init() { g_min_ord = 0xFFFFFFFFu; }

// ---------------- kernel 1: global min of img0 (float4) ----------------
__global__ void k_min(const float4* __restrict__ img, int n4) {
    float m = 3.402823466e38f;
    int stride = gridDim.x * blockDim.x;
    for (int i = blockIdx.x * blockDim.x + threadIdx.x; i < n4; i += stride) {
        float4 v = img[i];
        m = fminf(m, fminf(fminf(v.x, v.y), fminf(v.z, v.w)));
    }
    #pragma unroll
    for (int o = 16; o; o >>= 1) m = fminf(m, __shfl_xor_sync(0xFFFFFFFFu, m, o));
    __shared__ float sm[32];
    int lane = threadIdx.x & 31, w = threadIdx.x >> 5;
    if (lane == 0) sm[w] = m;
    __syncthreads();
    if (w == 0) {
        int nw = (blockDim.x + 31) >> 5;
        m = (lane < nw) ? sm[lane] : 3.402823466e38f;
        #pragma unroll
        for (int o = 16; o; o >>= 1) m = fminf(m, __shfl_xor_sync(0xFFFFFFFFu, m, o));
        if (lane == 0) atomicMin(&g_min_ord, f2ord(m));
    }
}

// ---------------- binning math (bit-exact vs reference) ----------------
__device__ __forceinline__ void stage_one(float v, float hmin, float dh,
                                          int& idx, float& xout) {
    if (v >= hmin && v <= 0.0f) {
        float x = __fdiv_rn(v - hmin, dh);
        idx = (int)floorf(x);
        xout = x;
    } else {
        idx = 0;
        xout = -1.0f;
    }
}

// ---------------- kernel 2: stage (bin once) + per-(chunk,bin) counts ----------
__global__ void k_stage(const float4* __restrict__ i0, const float4* __restrict__ i1,
                        int n) {
    __shared__ unsigned int sc0[256], sc1[256];
    int t = threadIdx.x;
    sc0[t] = 0u; sc1[t] = 0u;
    __syncthreads();

    float hmin = ord2f(g_min_ord);
    float dh   = __fdiv_rn(0.0f - hmin, 255.0f);
    int chunk = blockIdx.x;
    int i4 = (chunk << (CH_LG - 2)) + t;           // float4 index

    if (i4 * 4 < n) {
        float4 a = i0[i4];
        float4 b = i1[i4];
        int ia0, ia1, ia2, ia3, ib0, ib1, ib2, ib3;
        float xa0, xa1, xa2, xa3, xb0, xb1, xb2, xb3;
        stage_one(a.x, hmin, dh, ia0, xa0);
        stage_one(a.y, hmin, dh, ia1, xa1);
        stage_one(a.z, hmin, dh, ia2, xa2);
        stage_one(a.w, hmin, dh, ia3, xa3);
        stage_one(b.x, hmin, dh, ib0, xb0);
        stage_one(b.y, hmin, dh, ib1, xb1);
        stage_one(b.z, hmin, dh, ib2, xb2);
        stage_one(b.w, hmin, dh, ib3, xb3);
        if (xa0 >= 0.0f) atomicAdd(&sc0[ia0], 1u);
        if (xa1 >= 0.0f) atomicAdd(&sc0[ia1], 1u);
        if (xa2 >= 0.0f) atomicAdd(&sc0[ia2], 1u);
        if (xa3 >= 0.0f) atomicAdd(&sc0[ia3], 1u);
        if (xb0 >= 0.0f) atomicAdd(&sc1[ib0], 1u);
        if (xb1 >= 0.0f) atomicAdd(&sc1[ib1], 1u);
        if (xb2 >= 0.0f) atomicAdd(&sc1[ib2], 1u);
        if (xb3 >= 0.0f) atomicAdd(&sc1[ib3], 1u);
        ((float4*)g_sx0)[i4] = make_float4(xa0, xa1, xa2, xa3);
        ((float4*)g_sx1)[i4] = make_float4(xb0, xb1, xb2, xb3);
    }
    __syncthreads();
    g_cnt0[chunk * 256 + t] = sc0[t];              // coalesced [chunk][bin]
    g_cnt1[chunk * 256 + t] = sc1[t];
}

// ---------------- kernel 3a1: per-segment, per-bin prefix over chunks ----------
// grid (nseg, 2), 256 threads: thread t = bin t; segment = 256 chunks.
// 8-way batched loads (MLP=8) hide DRAM latency; the u32 carry is 1-cyc.
__global__ void k_scanA1(int nchunk) {
    int img = blockIdx.y;
    unsigned int* __restrict__ cnt = img ? g_cnt1 : g_cnt0;
    unsigned int* __restrict__ seg = img ? g_seg1 : g_seg0;
    int s = blockIdx.x;
    int t = threadIdx.x;

    int c0 = s << 8;
    int c1 = c0 + 256; if (c1 > nchunk) c1 = nchunk;
    unsigned int run = 0;
    int c = c0;
    for (; c + 8 <= c1; c += 8) {
        unsigned int v[8];
        #pragma unroll
        for (int u = 0; u < 8; u++) v[u] = cnt[(c + u) * 256 + t];
        #pragma unroll
        for (int u = 0; u < 8; u++) {
            cnt[(c + u) * 256 + t] = run;          // in-segment exclusive prefix
            run += v[u];
        }
    }
    for (; c < c1; c++) {
        unsigned int v = cnt[c * 256 + t];
        cnt[c * 256 + t] = run;
        run += v;
    }
    seg[s * 256 + t] = run;                        // segment total
}

// ---------------- kernel 3a2: per-bin scan over segment totals -----------------
// grid (8, 2), 32 threads: warp owns 32 bins; 8-way batched.
__global__ void k_scanA2(int nseg) {
    int lane = threadIdx.x;
    int bin  = (blockIdx.x << 5) + lane;
    int img  = blockIdx.y;
    unsigned int* __restrict__ seg = img ? g_seg1 : g_seg0;

    unsigned int run = 0;
    int s = 0;
    for (; s + 8 <= nseg; s += 8) {
        unsigned int v[8];
        #pragma unroll
        for (int u = 0; u < 8; u++) v[u] = seg[(s + u) * 256 + bin];
        #pragma unroll
        for (int u = 0; u < 8; u++) {
            seg[(s + u) * 256 + bin] = run;        // segment offset within bin
            run += v[u];
        }
    }
    for (; s < nseg; s++) {
        unsigned int v = seg[s * 256 + bin];
        seg[s * 256 + bin] = run;
        run += v;
    }
    g_tot[(img << 8) + bin] = run;
}

// ---------------- kernel 3b: 256-bin exclusive scan -> group starts ------------
__global__ void k_scanB() {
    __shared__ unsigned int s[512];
    int t = threadIdx.x;           // 512 threads: img = t>>8, bin = t&255
    s[t] = g_tot[t];
    __syncthreads();
    if ((t & 255) == 0) {
        int img = t >> 8;
        unsigned int* bs = img ? g_bs1 : g_bs0;
        unsigned int run = 0;
        for (int j = 0; j < 256; j++) {
            unsigned int v = s[(img << 8) + j];
            bs[j] = run;
            run += v;
        }
        bs[256] = run;
    }
}

// ---------------- kernel 4: stable placement, 3 barriers per 1024 elems --------
__global__ void k_place(int n) {
    __shared__ unsigned short s_cnt[32][256];      // [segment][bin] counts->starts
    __shared__ unsigned int s_gs[256];             // absolute starts for this chunk

    int img = blockIdx.y;
    const float* __restrict__ sxv = img ? g_sx1 : g_sx0;
    const unsigned int* __restrict__ cnt = img ? g_cnt1 : g_cnt0;
    const unsigned int* __restrict__ seg = img ? g_seg1 : g_seg0;
    const unsigned int* __restrict__ bs = img ? g_bs1 : g_bs0;
    float* __restrict__ outp = img ? g_sorted1 : g_sorted0;

    int chunk = blockIdx.x;
    int base  = chunk << CH_LG;
    int t     = threadIdx.x;
    int lane  = t & 31, w = t >> 5;

    #pragma unroll
    for (int k = 0; k < 16; k++)
        ((unsigned int*)s_cnt)[t + (k << 8)] = 0u;
    // absolute start = bin start + segment offset + in-segment chunk prefix
    s_gs[t] = bs[t] + seg[(chunk >> 8) * 256 + t] + cnt[chunk * 256 + t];
    __syncthreads();

    int   idxs[4];
    int   ranks[4];
    float ds[4];
    #pragma unroll
    for (int wv = 0; wv < 4; wv++) {
        int i = base + (wv << 8) + t;
        float x = (i < n) ? sxv[i] : -1.0f;
        bool keep = (x >= 0.0f);
        float fi = floorf(x);
        int idx = keep ? (int)fi : 0;
        float d = x - fi;                           // exact, same bits as stage
        unsigned int key = keep ? (unsigned int)idx : (0x1000u + (unsigned int)lane);
        unsigned int mask = __match_any_sync(0xFFFFFFFFu, key);
        int rank = __popc(mask & ((1u << lane) - 1u));
        int sg = (wv << 3) + w;
        if (keep && rank == 0)
            s_cnt[sg][idx] = (unsigned short)__popc(mask);
        idxs[wv] = idx; ranks[wv] = rank; ds[wv] = keep ? d : -1.0f;
    }
    __syncthreads();

    {
        unsigned int c[32];
        #pragma unroll
        for (int s2 = 0; s2 < 32; s2++) c[s2] = s_cnt[s2][t];
        unsigned int run = 0;
        #pragma unroll
        for (int s2 = 0; s2 < 32; s2++) { unsigned int v = c[s2]; c[s2] = run; run += v; }
        #pragma unroll
        for (int s2 = 0; s2 < 32; s2++) s_cnt[s2][t] = (unsigned short)c[s2];
    }
    __syncthreads();

    #pragma unroll
    for (int wv = 0; wv < 4; wv++) {
        if (ds[wv] >= 0.0f) {
            int sg = (wv << 3) + w;
            int idx = idxs[wv];
            unsigned int off = s_gs[idx] + (unsigned int)s_cnt[sg][idx]
                             + (unsigned int)ranks[wv];
            outp[off] = ds[wv];
        }
    }
}

// ---------------- kernel 5: exact sequential f32 fold, software-pipelined ------
__global__ void k_fold() {
    __shared__ __align__(16) float buf[2][FT];
    int img = blockIdx.y;
    const float* __restrict__ sd = img ? g_sorted1 : g_sorted0;
    const unsigned int* bs = img ? g_bs1 : g_bs0;
    float* h = img ? g_h1 : g_h0;
    int b = blockIdx.x;
    int t = threadIdx.x;

    unsigned int sA = bs[b], eA = bs[b + 1];
    unsigned int nA = eA - sA;                       // group b   -> weight (1-d)
    unsigned int sB = (b > 0) ? bs[b - 1] : 0u;
    unsigned int nB = (b > 0) ? (bs[b] - sB) : 0u;   // group b-1 -> weight d
    unsigned int total = nA + nB;
    int ntile = (int)((total + FT - 1) / FT);

    if (t >= 32 && ntile > 0) {
        unsigned int lim = (total < (unsigned int)FT) ? total : (unsigned int)FT;
        #pragma unroll 4
        for (unsigned int j = (unsigned int)(t - 32); j < lim; j += 128u)
            buf[0][j] = (j < nA) ? __fsub_rn(1.0f, sd[sA + j])
                                 : sd[sB + (j - nA)];
    }
    __syncthreads();

    float acc = 0.0f;
    for (int k = 0; k < ntile; k++) {
        int cur = k & 1;
        if (t >= 32) {
            if (k + 1 < ntile) {                     // prefetch next tile
                unsigned int nb = (unsigned int)(k + 1) * FT;
                unsigned int rem = total - nb;
                unsigned int lim = (rem < (unsigned int)FT) ? rem : (unsigned int)FT;
                #pragma unroll 4
                for (unsigned int j = (unsigned int)(t - 32); j < lim; j += 128u) {
                    unsigned int jj = nb + j;
                    buf[cur ^ 1][j] = (jj < nA) ? __fsub_rn(1.0f, sd[sA + jj])
                                                : sd[sB + (jj - nA)];
                }
            }
        } else if (t == 0) {
            unsigned int rem = total - (unsigned int)k * FT;
            if (rem >= (unsigned int)FT) {
                const float4* __restrict__ B4 = (const float4*)buf[cur];
                float4 ra[8], rb[8];
                #pragma unroll
                for (int u = 0; u < 8; u++) ra[u] = B4[u];
                #pragma unroll 1
                for (int g = 0; g < 128; g += 2) {
                    int n1 = (g + 1) << 3;
                    #pragma unroll
                    for (int u = 0; u < 8; u++) rb[u] = B4[n1 + u];
                    #pragma unroll
                    for (int u = 0; u < 8; u++) {
                        acc = __fadd_rn(acc, ra[u].x);
                        acc = __fadd_rn(acc, ra[u].y);
                        acc = __fadd_rn(acc, ra[u].z);
                        acc = __fadd_rn(acc, ra[u].w);
                    }
                    int n2 = ((g + 2) < 128 ? (g + 2) : 0) << 3;  // dummy at end
                    #pragma unroll
                    for (int u = 0; u < 8; u++) ra[u] = B4[n2 + u];
                    #pragma unroll
                    for (int u = 0; u < 8; u++) {
                        acc = __fadd_rn(acc, rb[u].x);
                        acc = __fadd_rn(acc, rb[u].y);
                        acc = __fadd_rn(acc, rb[u].z);
                        acc = __fadd_rn(acc, rb[u].w);
                    }
                }
            } else {
                const float* __restrict__ B = buf[cur];
                for (unsigned int i = 0; i < rem; i++)
                    acc = __fadd_rn(acc, B[i]);
            }
        }
        __syncthreads();
    }
    if (t == 0) h[b] = acc;
}

// ---------------- kernel 6: finalize (single thread, reference op-order) -------
__global__ void k_final(float* __restrict__ out) {
    if (threadIdx.x != 0 || blockIdx.x != 0) return;

    float S0 = 0.0f, S1 = 0.0f;
    for (int t = 0; t < NBIN; t++) S0 = __fadd_rn(S0, g_h0[t]);
    for (int t = 0; t < NBIN; t++) S1 = __fadd_rn(S1, g_h1[t]);

    float d0 = __fadd_rn(S0, EPSF);
    float d1 = __fadd_rn(S1, EPSF);

    float acc = 0.0f;
    for (int t = 0; t < NBIN; t++) {
        float h0n = __fdiv_rn(__fadd_rn(g_h0[t], EPSF), d0);
        float h1n = __fdiv_rn(__fadd_rn(g_h1[t], EPSF), d1);
        float num = __fadd_rn(h1n, EPSF);
        float qi  = __fdiv_rn(num, h1n);
        float qt  = __fdiv_rn(num, h0n);
        float inp = xla_logf(qi);
        float tgt = xla_logf(qt);
        float et  = xla_expf(tgt);
        float term = __fmul_rn(et, __fsub_rn(tgt, inp));
        acc = __fadd_rn(acc, term);
    }
    out[0] = __fdiv_rn(acc, 256.0f);
}

// ---------------- launch ----------------
extern "C" void kernel_launch(void* const* d_in, const int* in_sizes, int n_in,
                              void* d_out, int out_size) {
    const float* img0 = (const float*)d_in[0];
    const float* img1 = (const float*)d_in[1];
    float* out = (float*)d_out;
    int n = in_sizes[0];
    if (n > MAXN) n = MAXN;
    int nchunk = (n + CH - 1) / CH;
    int nseg = (nchunk + 255) >> 8;

    k_init  <<<1, 1>>>();
    k_min   <<<1184, 256>>>((const float4*)img0, n >> 2);
    k_stage <<<nchunk, 256>>>((const float4*)img0, (const float4*)img1, n);
    k_scanA1<<<dim3(nseg, 2), 256>>>(nchunk);
    k_scanA2<<<dim3(8, 2), 32>>>(nseg);
    k_scanB <<<1, 512>>>();
    k_place <<<dim3(nchunk, 2), 256>>>(n);
    k_fold  <<<dim3(256, 2), 160>>>();
    k_final <<<1, 32>>>(out);
}